// round 15
// baseline (speedup 1.0000x reference)
#include <cuda_runtime.h>
#include <cuda_fp16.h>
#include <cstdint>

#define EMB_DIM 300
#define KP      304
#define NTOT    2048
#define MTOT    32768
#define MTILE   128
#define NCHUNK  256
#define NCHUNKS (NTOT / NCHUNK)      // 8
#define NGRP    3                    // K-groups per chunk (7/6/6 ksteps)
#define NSTEPS  (NCHUNKS * NGRP)     // 24 pipeline steps
#define A_ROWB  608                  // 304 halves, unpadded, swizzled
#define B_ROWB  128                  // 64 halves per slice row, swizzled
#define B_SLICE (300 * B_ROWB)       // 38400 (rows 300-303 never loaded)
#define B_TOT   (4 * B_SLICE)        // 153600
#define A_BYTES (MTILE * A_ROWB)     // 77824
#define SMEM_BYTES (B_TOT + A_BYTES) // 231424 <= 232448
#define SCALE 45.254833995939045f

__device__ __half g_Wh[KP * NTOT];   // fp16 W, K zero-padded rows
__device__ float  g_bs[NTOT];        // bias * scale

__global__ void prep(const float* __restrict__ W, const float* __restrict__ b) {
    int i = blockIdx.x * blockDim.x + threadIdx.x;
    if (i < KP * NTOT) {
        int k = i / NTOT, n = i % NTOT;
        g_Wh[i] = __float2half_rn((k < EMB_DIM) ? W[k * NTOT + n] : 0.0f);
    }
    if (i < NTOT) g_bs[i] = b[i] * SCALE;
}

__device__ __forceinline__ void ldm_x4(uint32_t* r, uint32_t a) {
    asm volatile("ldmatrix.sync.aligned.m8n8.x4.shared.b16 {%0,%1,%2,%3}, [%4];"
                 : "=r"(r[0]), "=r"(r[1]), "=r"(r[2]), "=r"(r[3]) : "r"(a));
}
__device__ __forceinline__ void ldm_x4_t(uint32_t* r, uint32_t a) {
    asm volatile("ldmatrix.sync.aligned.m8n8.x4.trans.shared.b16 {%0,%1,%2,%3}, [%4];"
                 : "=r"(r[0]), "=r"(r[1]), "=r"(r[2]), "=r"(r[3]) : "r"(a));
}
__device__ __forceinline__ void mma16816(float* d, const uint32_t* a, const uint32_t* b) {
    asm volatile("mma.sync.aligned.m16n8k16.row.col.f32.f16.f16.f32 "
                 "{%0,%1,%2,%3}, {%4,%5,%6,%7}, {%8,%9}, {%0,%1,%2,%3};"
                 : "+f"(d[0]), "+f"(d[1]), "+f"(d[2]), "+f"(d[3])
                 : "r"(a[0]), "r"(a[1]), "r"(a[2]), "r"(a[3]),
                   "r"(b[0]), "r"(b[1]));
}

// cp.async one K-group of a slice. Row windows: g0 [0,112) g1 [112,208)
// g2 [208,300). The 4 warps of the slice group (wm 0..3) split each window.
__device__ __forceinline__ void issue_group(uint32_t bSliceU, int n0, int g,
                                            int wm, int lane) {
    int start = (g == 0) ? 0 : (g == 1 ? 112 : 208);
    int cnt   = (g == 0) ? 28 : (g == 1 ? 24 : 23);   // per-warp rows
    start += wm * cnt;
    int seg = lane & 7;
    int r0  = start + (lane >> 3);
    int iters = (cnt + 3) >> 2;
    for (int it = 0; it < iters; ++it) {
        int row = r0 + it * 4;
        if (row < start + cnt) {
            uint32_t dst = bSliceU + (uint32_t)row * B_ROWB
                         + (uint32_t)((seg ^ (row & 7)) * 16);
            size_t gsrc = __cvta_generic_to_global(
                g_Wh + (size_t)row * NTOT + n0 + seg * 8);
            asm volatile("cp.async.cg.shared.global [%0], [%1], 16;"
                         :: "r"(dst), "l"(gsrc));
        }
    }
}

// fully-unrolled K-group compute: ksteps [KS0, KS0+KSN), warp tile m32 x n64
template <int KS0, int KSN>
__device__ __forceinline__ void compute_group(
    const uint32_t aRowByte[2], uint32_t bRowByte, const uint32_t boff[4],
    int cb, int rq, float (&acc)[2][8][4]) {
    #pragma unroll
    for (int kk = 0; kk < KSN; ++kk) {
        const int ks = KS0 + kk;
        uint32_t cc = (uint32_t)(ks * 2 + cb);
        uint32_t aoff = ((cc < 32u) ? (cc ^ (uint32_t)rq) : cc) * 16u;
        uint32_t af[2][4], bf[4][4];
        #pragma unroll
        for (int mt = 0; mt < 2; ++mt)
            ldm_x4(af[mt], aRowByte[mt] + aoff);
        uint32_t bks = bRowByte + (uint32_t)(ks * 16 * B_ROWB);
        #pragma unroll
        for (int p = 0; p < 4; ++p)
            ldm_x4_t(bf[p], bks + boff[p]);
        #pragma unroll
        for (int mt = 0; mt < 2; ++mt)
            #pragma unroll
            for (int nt = 0; nt < 8; ++nt) {
                uint32_t bb[2] = { bf[nt >> 1][(nt & 1) * 2],
                                   bf[nt >> 1][(nt & 1) * 2 + 1] };
                mma16816(acc[mt][nt], af[mt], bb);
            }
    }
}

__global__ __launch_bounds__(512, 1)
void gemm_kernel(const int* __restrict__ x, const float* __restrict__ emb,
                 float* __restrict__ out) {
    extern __shared__ char sm[];
    const uint32_t smem_u = (uint32_t)__cvta_generic_to_shared(sm);
    const uint32_t aU = smem_u + B_TOT;

    const int tid  = threadIdx.x;
    const int lane = tid & 31, wid = tid >> 5;       // 16 warps
    const int wm = wid & 3;                          // 0..3 : m32 band
    const int wn = wid >> 2;                         // 0..3 : n64 slice group
    const int m0 = blockIdx.x * MTILE;
    const uint32_t bSliceU = smem_u + (uint32_t)wn * B_SLICE;

    // ---- prologue: steps 0,1 (chunk0 groups 0,1) in flight ----
    issue_group(bSliceU, wn * 64, 0, wm, lane);
    asm volatile("cp.async.commit_group;" ::: "memory");
    issue_group(bSliceU, wn * 64, 1, wm, lane);
    asm volatile("cp.async.commit_group;" ::: "memory");

    // ---- gather A (swizzled, unpadded rows): 128 rows, 4 threads/row ----
    {
        int r = tid >> 2;
        int token = x[m0 + r];
        const float4* src = (const float4*)(emb + (size_t)token * EMB_DIM);
        char* arow = sm + B_TOT + r * A_ROWB;
        int r7 = r & 7;
        #pragma unroll
        for (int j = (tid & 3); j < 75; j += 4) {    // 75 float4 per row
            float4 v = src[j];
            int c16 = j >> 1;
            int swc = (c16 < 32) ? (c16 ^ r7) : c16;
            char* dp = arow + swc * 16 + (j & 1) * 8;
            ((__half2*)dp)[0] = __floats2half2_rn(v.x, v.y);
            ((__half2*)dp)[1] = __floats2half2_rn(v.z, v.w);
        }
        if ((tid & 3) == 0) {                        // zero k 300..303 (seg 37, hi 8B)
            char* dp = arow + 37 * 16 + 8;
            ((__half2*)dp)[0] = __half2half2(__float2half(0.0f));
            ((__half2*)dp)[1] = __half2half2(__float2half(0.0f));
        }
    }
    __syncthreads();    // A visible to all; B is group-self-synced from here on

    // ---- lane constants ----
    const int bq = lane >> 3, rq = lane & 7, cb = bq >> 1;
    uint32_t aRowByte[2];
    #pragma unroll
    for (int mt = 0; mt < 2; ++mt)
        aRowByte[mt] = aU + (uint32_t)((wm * 32 + mt * 16 + (bq & 1) * 8 + rq) * A_ROWB);
    const uint32_t bRowByte = bSliceU + (uint32_t)(((bq & 1) * 8 + rq) * B_ROWB);
    uint32_t boff[4];
    #pragma unroll
    for (int p = 0; p < 4; ++p)
        boff[p] = (uint32_t)(((p * 2 + cb) ^ rq) * 16);
    const int barId = wn + 1;

    float acc[2][8][4];
    #pragma unroll
    for (int mt = 0; mt < 2; ++mt)
        #pragma unroll
        for (int nt = 0; nt < 8; ++nt)
            #pragma unroll
            for (int q = 0; q < 4; ++q) acc[mt][nt][q] = 0.0f;

    int s = 0;
    #pragma unroll 1
    for (int c = 0; c < NCHUNKS; ++c) {
        #pragma unroll 1
        for (int g = 0; g < NGRP; ++g, ++s) {
            // data for step s = commit #(s+1); keep <=1 pending
            asm volatile("cp.async.wait_group 1;" ::: "memory");
            asm volatile("bar.sync %0, 128;" :: "r"(barId) : "memory");

            if (g == 0)      compute_group<0, 7>(aRowByte, bRowByte, boff, cb, rq, acc);
            else if (g == 1) compute_group<7, 6>(aRowByte, bRowByte, boff, cb, rq, acc);
            else             compute_group<13, 6>(aRowByte, bRowByte, boff, cb, rq, acc);

            // refill region consumed at step s-1 (== region of step s+2)
            int s2 = s + 2;
            if (s2 < NSTEPS) {
                int c2 = s2 / NGRP, g2 = s2 - c2 * NGRP;
                issue_group(bSliceU, c2 * NCHUNK + wn * 64, g2, wm, lane);
            }
            asm volatile("cp.async.commit_group;" ::: "memory");
        }

        // ---- epilogue for chunk c (no barrier; overlaps other groups) ----
        int n0 = c * NCHUNK;
        #pragma unroll
        for (int nt = 0; nt < 8; ++nt) {
            int col = n0 + wn * 64 + nt * 8 + (lane & 3) * 2;
            float2 cbia = *(const float2*)(g_bs + col);
            #pragma unroll
            for (int mt = 0; mt < 2; ++mt) {
                int row = m0 + wm * 32 + mt * 16 + (lane >> 2);
                float2 v0 = { fmaf(acc[mt][nt][0], SCALE, cbia.x),
                              fmaf(acc[mt][nt][1], SCALE, cbia.y) };
                float2 v1 = { fmaf(acc[mt][nt][2], SCALE, cbia.x),
                              fmaf(acc[mt][nt][3], SCALE, cbia.y) };
                *(float2*)(out + (size_t)row * NTOT + col)       = v0;
                *(float2*)(out + (size_t)(row + 8) * NTOT + col) = v1;
                acc[mt][nt][0] = 0.0f; acc[mt][nt][1] = 0.0f;
                acc[mt][nt][2] = 0.0f; acc[mt][nt][3] = 0.0f;
            }
        }
    }
}

extern "C" void kernel_launch(void* const* d_in, const int* in_sizes, int n_in,
                              void* d_out, int out_size) {
    const int*   x    = (const int*)  d_in[0];
    const float* emb  = (const float*)d_in[1];
    const float* W    = (const float*)d_in[2];
    const float* bias = (const float*)d_in[3];
    float*       out  = (float*)      d_out;

    cudaFuncSetAttribute(gemm_kernel, cudaFuncAttributeMaxDynamicSharedMemorySize,
                         SMEM_BYTES);

    prep<<<(KP * NTOT + 255) / 256, 256>>>(W, bias);
    gemm_kernel<<<MTOT / MTILE, 512, SMEM_BYTES>>>(x, emb, out);
}

// round 16
// speedup vs baseline: 1.0178x; 1.0178x over previous
#include <cuda_runtime.h>
#include <cuda_fp16.h>
#include <cstdint>

#define EMB_DIM 300
#define KP      304
#define NTOT    2048
#define MTOT    32768
#define MTILE   128
#define NCHUNK  256
#define NCHUNKS (NTOT / NCHUNK)      // 8
#define NGRP    3                    // K-groups per chunk (7/6/6 ksteps)
#define TOTU    ((MTOT / MTILE) * NCHUNKS)   // 2048 units, m-major
#define GRIDX   148                  // persistent: one CTA per SM
#define A_ROWB  608                  // 304 halves, unpadded, swizzled
#define B_ROWB  128                  // 64 halves per slice row, swizzled
#define B_SLICE (300 * B_ROWB)       // 38400 (rows 300-303 never loaded)
#define B_TOT   (4 * B_SLICE)        // 153600
#define A_BYTES (MTILE * A_ROWB)     // 77824
#define SMEM_BYTES (B_TOT + A_BYTES) // 231424 <= 232448
#define SCALE 45.254833995939045f

__device__ __half g_Wh[KP * NTOT];   // fp16 W, K zero-padded rows
__device__ float  g_bs[NTOT];        // bias * scale

__global__ void prep(const float* __restrict__ W, const float* __restrict__ b) {
    int i = blockIdx.x * blockDim.x + threadIdx.x;
    if (i < KP * NTOT) {
        int k = i / NTOT, n = i % NTOT;
        g_Wh[i] = __float2half_rn((k < EMB_DIM) ? W[k * NTOT + n] : 0.0f);
    }
    if (i < NTOT) g_bs[i] = b[i] * SCALE;
}

__device__ __forceinline__ void ldm_x4(uint32_t* r, uint32_t a) {
    asm volatile("ldmatrix.sync.aligned.m8n8.x4.shared.b16 {%0,%1,%2,%3}, [%4];"
                 : "=r"(r[0]), "=r"(r[1]), "=r"(r[2]), "=r"(r[3]) : "r"(a));
}
__device__ __forceinline__ void ldm_x4_t(uint32_t* r, uint32_t a) {
    asm volatile("ldmatrix.sync.aligned.m8n8.x4.trans.shared.b16 {%0,%1,%2,%3}, [%4];"
                 : "=r"(r[0]), "=r"(r[1]), "=r"(r[2]), "=r"(r[3]) : "r"(a));
}
__device__ __forceinline__ void mma16816(float* d, const uint32_t* a, const uint32_t* b) {
    asm volatile("mma.sync.aligned.m16n8k16.row.col.f32.f16.f16.f32 "
                 "{%0,%1,%2,%3}, {%4,%5,%6,%7}, {%8,%9}, {%0,%1,%2,%3};"
                 : "+f"(d[0]), "+f"(d[1]), "+f"(d[2]), "+f"(d[3])
                 : "r"(a[0]), "r"(a[1]), "r"(a[2]), "r"(a[3]),
                   "r"(b[0]), "r"(b[1]));
}

// cp.async one K-group of a slice. Row windows: g0 [0,112) g1 [112,208)
// g2 [208,300). The 4 warps of the slice group (wm 0..3) split each window.
__device__ __forceinline__ void issue_group(uint32_t bSliceU, int n0, int g,
                                            int wm, int lane) {
    int start = (g == 0) ? 0 : (g == 1 ? 112 : 208);
    int cnt   = (g == 0) ? 28 : (g == 1 ? 24 : 23);   // per-warp rows
    start += wm * cnt;
    int seg = lane & 7;
    int r0  = start + (lane >> 3);
    int iters = (cnt + 3) >> 2;
    for (int it = 0; it < iters; ++it) {
        int row = r0 + it * 4;
        if (row < start + cnt) {
            uint32_t dst = bSliceU + (uint32_t)row * B_ROWB
                         + (uint32_t)((seg ^ (row & 7)) * 16);
            size_t gsrc = __cvta_generic_to_global(
                g_Wh + (size_t)row * NTOT + n0 + seg * 8);
            asm volatile("cp.async.cg.shared.global [%0], [%1], 16;"
                         :: "r"(dst), "l"(gsrc));
        }
    }
}

// fully-unrolled K-group compute: ksteps [KS0, KS0+KSN), warp tile m32 x n64
template <int KS0, int KSN>
__device__ __forceinline__ void compute_group(
    const uint32_t aRowByte[2], uint32_t bRowByte, const uint32_t boff[4],
    int cb, int rq, float (&acc)[2][8][4]) {
    #pragma unroll
    for (int kk = 0; kk < KSN; ++kk) {
        const int ks = KS0 + kk;
        uint32_t cc = (uint32_t)(ks * 2 + cb);
        uint32_t aoff = ((cc < 32u) ? (cc ^ (uint32_t)rq) : cc) * 16u;
        uint32_t af[2][4], bf[4][4];
        #pragma unroll
        for (int mt = 0; mt < 2; ++mt)
            ldm_x4(af[mt], aRowByte[mt] + aoff);
        uint32_t bks = bRowByte + (uint32_t)(ks * 16 * B_ROWB);
        #pragma unroll
        for (int p = 0; p < 4; ++p)
            ldm_x4_t(bf[p], bks + boff[p]);
        #pragma unroll
        for (int mt = 0; mt < 2; ++mt)
            #pragma unroll
            for (int nt = 0; nt < 8; ++nt) {
                uint32_t bb[2] = { bf[nt >> 1][(nt & 1) * 2],
                                   bf[nt >> 1][(nt & 1) * 2 + 1] };
                mma16816(acc[mt][nt], af[mt], bb);
            }
    }
}

// gather one A m-tile (128 rows) into swizzled smem; 512 threads cooperate
__device__ __forceinline__ void gather_a(char* smA, const int* __restrict__ x,
                                         const float* __restrict__ emb,
                                         int m0, int tid) {
    int r = tid >> 2;
    int token = x[m0 + r];
    const float4* src = (const float4*)(emb + (size_t)token * EMB_DIM);
    char* arow = smA + r * A_ROWB;
    int r7 = r & 7;
    #pragma unroll
    for (int j = (tid & 3); j < 75; j += 4) {        // 75 float4 per row
        float4 v = src[j];
        int c16 = j >> 1;
        int swc = (c16 < 32) ? (c16 ^ r7) : c16;
        char* dp = arow + swc * 16 + (j & 1) * 8;
        ((__half2*)dp)[0] = __floats2half2_rn(v.x, v.y);
        ((__half2*)dp)[1] = __floats2half2_rn(v.z, v.w);
    }
    if ((tid & 3) == 0) {                            // zero k 300..303
        char* dp = arow + 37 * 16 + 8;
        ((__half2*)dp)[0] = __half2half2(__float2half(0.0f));
        ((__half2*)dp)[1] = __half2half2(__float2half(0.0f));
    }
}

__global__ __launch_bounds__(512, 1)
void gemm_kernel(const int* __restrict__ x, const float* __restrict__ emb,
                 float* __restrict__ out) {
    extern __shared__ char sm[];
    const uint32_t smem_u = (uint32_t)__cvta_generic_to_shared(sm);
    const uint32_t aU = smem_u + B_TOT;
    char* smA = sm + B_TOT;

    const int tid  = threadIdx.x;
    const int lane = tid & 31, wid = tid >> 5;       // 16 warps
    const int wm = wid & 3;                          // 0..3 : m32 band
    const int wn = wid >> 2;                         // 0..3 : n64 slice group
    const uint32_t bSliceU = smem_u + (uint32_t)wn * B_SLICE;

    // persistent unit range: units m-major (u = m*8 + chunk)
    const int bid = blockIdx.x;
    const int u0 = (bid * TOTU) / GRIDX;
    const int u1 = ((bid + 1) * TOTU) / GRIDX;
    const int nsteps = (u1 - u0) * NGRP;

    // ---- prologue: steps 0,1 = unit u0 groups 0,1 in flight ----
    {
        int n00 = (u0 & 7) * NCHUNK + wn * 64;
        issue_group(bSliceU, n00, 0, wm, lane);
        asm volatile("cp.async.commit_group;" ::: "memory");
        issue_group(bSliceU, n00, 1, wm, lane);
        asm volatile("cp.async.commit_group;" ::: "memory");
    }

    // ---- lane constants ----
    const int bq = lane >> 3, rq = lane & 7, cb = bq >> 1;
    uint32_t aRowByte[2];
    #pragma unroll
    for (int mt = 0; mt < 2; ++mt)
        aRowByte[mt] = aU + (uint32_t)((wm * 32 + mt * 16 + (bq & 1) * 8 + rq) * A_ROWB);
    const uint32_t bRowByte = bSliceU + (uint32_t)(((bq & 1) * 8 + rq) * B_ROWB);
    uint32_t boff[4];
    #pragma unroll
    for (int p = 0; p < 4; ++p)
        boff[p] = (uint32_t)(((p * 2 + cb) ^ rq) * 16);
    const int barId = wn + 1;

    float acc[2][8][4];
    #pragma unroll
    for (int mt = 0; mt < 2; ++mt)
        #pragma unroll
        for (int nt = 0; nt < 8; ++nt)
            #pragma unroll
            for (int q = 0; q < 4; ++q) acc[mt][nt][q] = 0.0f;

    int mPrev = -1;
    int s = 0;
    #pragma unroll 1
    for (int u = u0; u < u1; ++u) {
        const int m8 = u >> 3;
        if (m8 != mPrev) {
            __syncthreads();                 // all warps done reading old A
            gather_a(smA, x, emb, m8 * MTILE, tid);
            __syncthreads();                 // new A visible
            mPrev = m8;
        }

        #pragma unroll 1
        for (int g = 0; g < NGRP; ++g, ++s) {
            // data for step s = commit #(s+1); keep <=1 pending
            asm volatile("cp.async.wait_group 1;" ::: "memory");
            asm volatile("bar.sync %0, 128;" :: "r"(barId) : "memory");

            if (g == 0)      compute_group<0, 7>(aRowByte, bRowByte, boff, cb, rq, acc);
            else if (g == 1) compute_group<7, 6>(aRowByte, bRowByte, boff, cb, rq, acc);
            else             compute_group<13, 6>(aRowByte, bRowByte, boff, cb, rq, acc);

            // refill region consumed at step s-1 (== region of step s+2)
            int s2 = s + 2;
            if (s2 < nsteps) {
                int uu = u0 + s2 / NGRP, gg = s2 - (s2 / NGRP) * NGRP;
                issue_group(bSliceU, (uu & 7) * NCHUNK + wn * 64, gg, wm, lane);
            }
            asm volatile("cp.async.commit_group;" ::: "memory");
        }

        // ---- epilogue for this unit (no barrier; overlaps other groups) ----
        int n0 = (u & 7) * NCHUNK;
        int m0 = m8 * MTILE;
        #pragma unroll
        for (int nt = 0; nt < 8; ++nt) {
            int col = n0 + wn * 64 + nt * 8 + (lane & 3) * 2;
            float2 cbia = *(const float2*)(g_bs + col);
            #pragma unroll
            for (int mt = 0; mt < 2; ++mt) {
                int row = m0 + wm * 32 + mt * 16 + (lane >> 2);
                float2 v0 = { fmaf(acc[mt][nt][0], SCALE, cbia.x),
                              fmaf(acc[mt][nt][1], SCALE, cbia.y) };
                float2 v1 = { fmaf(acc[mt][nt][2], SCALE, cbia.x),
                              fmaf(acc[mt][nt][3], SCALE, cbia.y) };
                *(float2*)(out + (size_t)row * NTOT + col)       = v0;
                *(float2*)(out + (size_t)(row + 8) * NTOT + col) = v1;
                acc[mt][nt][0] = 0.0f; acc[mt][nt][1] = 0.0f;
                acc[mt][nt][2] = 0.0f; acc[mt][nt][3] = 0.0f;
            }
        }
    }
}

extern "C" void kernel_launch(void* const* d_in, const int* in_sizes, int n_in,
                              void* d_out, int out_size) {
    const int*   x    = (const int*)  d_in[0];
    const float* emb  = (const float*)d_in[1];
    const float* W    = (const float*)d_in[2];
    const float* bias = (const float*)d_in[3];
    float*       out  = (float*)      d_out;

    cudaFuncSetAttribute(gemm_kernel, cudaFuncAttributeMaxDynamicSharedMemorySize,
                         SMEM_BYTES);

    prep<<<(KP * NTOT + 255) / 256, 256>>>(W, bias);
    gemm_kernel<<<GRIDX, 512, SMEM_BYTES>>>(x, emb, out);
}